// round 14
// baseline (speedup 1.0000x reference)
#include <cuda_runtime.h>
#include <cuda_bf16.h>

#define D 8192
#define BATCH 4096
#define ROWS_PER_BLOCK 16

__device__ float d_z[D];   // after FWHT bits 10..12, s1[0] folded
__device__ float d_w[D];   // final weight row (all stages + s2)

// ---------------------------------------------------------------------------
// K1 (R9's proven producer): softplus + s1[0] + FWHT bits 10..12.
// Thread i owns {i + j*1024 : j=0..7}; perfect coalescing, 24-deep load MLP,
// barrier-free, 16 blocks x 64 threads, PDL trigger at top.
// ---------------------------------------------------------------------------
__global__ __launch_bounds__(64, 1)
void stage1_kernel(const float* __restrict__ s1,
                   const float* __restrict__ g_mu,
                   const float* __restrict__ g_rho,
                   const float* __restrict__ eps) {
#if __CUDA_ARCH__ >= 900
    cudaTriggerProgrammaticLaunchCompletion();   // successor may launch now
#endif
    const int i = blockIdx.x * 64 + threadIdx.x;     // 0..1023
    const float s10 = __ldg(s1);

    float rh[8], mu[8], ep[8];
    #pragma unroll
    for (int j = 0; j < 8; j++) {                    // issue all loads first
        rh[j] = __ldg(g_rho + i + j * 1024);
        mu[j] = __ldg(g_mu  + i + j * 1024);
        ep[j] = __ldg(eps   + i + j * 1024);
    }
    float r[8];
    #pragma unroll
    for (int j = 0; j < 8; j++) {
        float sp = fmaxf(rh[j], 0.0f) + __logf(1.0f + __expf(-fabsf(rh[j])));
        r[j] = s10 * fmaf(sp, ep[j], mu[j]);
    }
    #pragma unroll
    for (int s = 1; s < 8; s <<= 1) {                // bits 10..12
        #pragma unroll
        for (int j = 0; j < 8; j++) {
            if (!(j & s)) {
                float a = r[j], b = r[j | s];
                r[j]     = a + b;
                r[j | s] = a - b;
            }
        }
    }
    #pragma unroll
    for (int j = 0; j < 8; j++)
        d_z[i + j * 1024] = r[j];                    // coalesced
}

// ---------------------------------------------------------------------------
// K2: FWHT bits 0..9 + s2, barrier-free, register-only. 8 blocks x 32 threads.
// Element t = m*32 + lane within this block's 1024-chunk: lane = bits 0..4
// (shfl butterflies, coalesced gmem), m = bits 5..9 (in-register butterflies).
// Trigger at top; s2 preloaded before the PDL sync; d_z loads are L2 hits.
// ---------------------------------------------------------------------------
__global__ __launch_bounds__(32, 1)
void stage2_kernel(const float* __restrict__ s2) {
#if __CUDA_ARCH__ >= 900
    cudaTriggerProgrammaticLaunchCompletion();   // successor may launch now
#endif
    const int lane = threadIdx.x;
    const int sb   = blockIdx.x * 1024;

    float s2v[32];
    #pragma unroll
    for (int m = 0; m < 32; m++)
        s2v[m] = __ldg(s2 + sb + m * 32 + lane);     // independent of K1

#if __CUDA_ARCH__ >= 900
    cudaGridDependencySynchronize();                 // wait for d_z
#endif

    float v[32];
    #pragma unroll
    for (int m = 0; m < 32; m++)
        v[m] = d_z[sb + m * 32 + lane];              // coalesced, L2-hot

    // bits 0..4 via shfl.xor on lane
    #pragma unroll
    for (int mk = 1; mk <= 16; mk <<= 1) {
        const float sgn = (lane & mk) ? -1.0f : 1.0f;
        #pragma unroll
        for (int m = 0; m < 32; m++) {
            float o = __shfl_xor_sync(0xffffffffu, v[m], mk);
            v[m] = fmaf(sgn, v[m], o);
        }
    }
    // bits 5..9: 32-point FWHT over register index m
    #pragma unroll
    for (int s = 1; s < 32; s <<= 1) {
        #pragma unroll
        for (int m = 0; m < 32; m++) {
            if (!(m & s)) {
                float a = v[m], b = v[m | s];
                v[m]     = a + b;
                v[m | s] = a - b;
            }
        }
    }

    #pragma unroll
    for (int m = 0; m < 32; m++)
        d_w[sb + m * 32 + lane] = s2v[m] * v[m];     // coalesced
}

// ---------------------------------------------------------------------------
// K3: pure rank-1 outer product (R1's body, measured 20.8us — store roofline).
// out[b][j] = x[b] * w[j].  grid (8,256) x 256, 16 rows/block, __stcs stores.
// x preloaded before the PDL sync.
// ---------------------------------------------------------------------------
__global__ __launch_bounds__(256)
void outer_kernel(const float* __restrict__ x, float* __restrict__ out) {
    const int jbase = blockIdx.x * 1024 + threadIdx.x * 4;
    const int b0    = blockIdx.y * ROWS_PER_BLOCK;

    float xs[ROWS_PER_BLOCK];
    #pragma unroll
    for (int q = 0; q < ROWS_PER_BLOCK; q++)
        xs[q] = __ldg(x + b0 + q);

#if __CUDA_ARCH__ >= 900
    cudaGridDependencySynchronize();                 // wait for d_w
#endif

    const float4 w4 = *(const float4*)(d_w + jbase);

    #pragma unroll
    for (int q = 0; q < ROWS_PER_BLOCK; q++) {
        float xv = xs[q];
        float4 o = make_float4(xv * w4.x, xv * w4.y, xv * w4.z, xv * w4.w);
        // 134 MB output, never re-read -> streaming (evict-first) store
        __stcs((float4*)(out + (size_t)(b0 + q) * D + jbase), o);
    }
}

extern "C" void kernel_launch(void* const* d_in, const int* in_sizes, int n_in,
                              void* d_out, int out_size) {
    const float* x     = (const float*)d_in[0];  // (4096, 1)
    const float* s1    = (const float*)d_in[1];  // (8192,)
    const float* s2    = (const float*)d_in[2];  // (8192,)
    const float* g_mu  = (const float*)d_in[3];  // (8192,)
    const float* g_rho = (const float*)d_in[4];  // (8192,)
    const float* eps   = (const float*)d_in[5];  // (8192,)
    float* out = (float*)d_out;                  // (4096, 8192) f32

    cudaLaunchAttribute attr;
    attr.id = cudaLaunchAttributeProgrammaticStreamSerialization;
    attr.val.programmaticStreamSerializationAllowed = 1;

    stage1_kernel<<<16, 64>>>(s1, g_mu, g_rho, eps);

    {
        cudaLaunchConfig_t cfg = {};
        cfg.gridDim  = dim3(8, 1, 1);
        cfg.blockDim = dim3(32, 1, 1);
        cfg.stream   = 0;
        cfg.attrs = &attr; cfg.numAttrs = 1;
        cudaLaunchKernelEx(&cfg, stage2_kernel, s2);
    }
    {
        cudaLaunchConfig_t cfg = {};
        cfg.gridDim  = dim3(D / 1024, BATCH / ROWS_PER_BLOCK, 1);  // (8, 256)
        cfg.blockDim = dim3(256, 1, 1);
        cfg.stream   = 0;
        cfg.attrs = &attr; cfg.numAttrs = 1;
        cudaLaunchKernelEx(&cfg, outer_kernel, x, out);
    }
}

// round 15
// speedup vs baseline: 1.0638x; 1.0638x over previous
#include <cuda_runtime.h>
#include <cuda_bf16.h>

#define D 8192
#define BATCH 4096
#define ROWS_PER_BLOCK 16

// z: FWHT bits 0..4 and 10..12 applied, s1[0] folded.
__device__ float d_z[D];

// ---------------------------------------------------------------------------
// Producer (R9's proven-hidden shape: 16 blocks x 64 threads, barrier-free,
// trigger at top): softplus + s1[0] + FWHT bits 10..12 (in-register over j)
// AND bits 0..4 (shfl.xor over lane — free ALU work under the load shadows).
// Thread i owns {i + j*1024 : j=0..7}; lane = element bits 0..4. Coalesced.
// ---------------------------------------------------------------------------
__global__ __launch_bounds__(64, 1)
void producer_kernel(const float* __restrict__ s1,
                     const float* __restrict__ g_mu,
                     const float* __restrict__ g_rho,
                     const float* __restrict__ eps) {
#if __CUDA_ARCH__ >= 900
    cudaTriggerProgrammaticLaunchCompletion();   // successor may launch now
#endif
    const int i    = blockIdx.x * 64 + threadIdx.x;  // 0..1023
    const int lane = threadIdx.x & 31;               // = element bits 0..4
    const float s10 = __ldg(s1);

    float rh[8], mu[8], ep[8];
    #pragma unroll
    for (int j = 0; j < 8; j++) {                    // issue all loads first
        rh[j] = __ldg(g_rho + i + j * 1024);
        mu[j] = __ldg(g_mu  + i + j * 1024);
        ep[j] = __ldg(eps   + i + j * 1024);
    }
    float r[8];
    #pragma unroll
    for (int j = 0; j < 8; j++) {
        float sp = fmaxf(rh[j], 0.0f) + __logf(1.0f + __expf(-fabsf(rh[j])));
        r[j] = s10 * fmaf(sp, ep[j], mu[j]);
    }
    // bits 10..12: 8-point FWHT over j (in-register)
    #pragma unroll
    for (int s = 1; s < 8; s <<= 1) {
        #pragma unroll
        for (int j = 0; j < 8; j++) {
            if (!(j & s)) {
                float a = r[j], b = r[j | s];
                r[j]     = a + b;
                r[j | s] = a - b;
            }
        }
    }
    // bits 0..4: shfl.xor butterflies on lane
    #pragma unroll
    for (int m = 1; m <= 16; m <<= 1) {
        const float sgn = (lane & m) ? -1.0f : 1.0f;
        #pragma unroll
        for (int j = 0; j < 8; j++) {
            float o = __shfl_xor_sync(0xffffffffu, r[j], m);
            r[j] = fmaf(sgn, r[j], o);
        }
    }
    #pragma unroll
    for (int j = 0; j < 8; j++)
        d_z[i + j * 1024] = r[j];                    // coalesced
}

// ---------------------------------------------------------------------------
// Outer: remaining FWHT bits 5..6 (in-register) + bits 7..9 (8-way signed
// smem combine: w[c*128+t] = sum_c' (-1)^popc(c&c') pre[c'*128+t], Sylvester
// H_8, warp-uniform signs) + s2 + rank-1 outer product. ONE sync.
// grid (8,256) x 256, 16 rows/block, __stcs streaming stores.
// PDL: x and s2 preloaded BEFORE the grid dependency sync.
// ---------------------------------------------------------------------------
__global__ __launch_bounds__(256)
void outer_kernel(const float* __restrict__ x,
                  const float* __restrict__ s2,
                  float* __restrict__ out) {
    __shared__ float sw[1024];
    const int tid  = threadIdx.x;
    const int lane = tid & 31;
    const int r    = tid >> 5;                    // warp = chunk bits 7..9
    const int jb   = blockIdx.x * 1024;
    const int b0   = blockIdx.y * ROWS_PER_BLOCK;

    // ---- prologue independent of the producer ----
    float xs[ROWS_PER_BLOCK];
    #pragma unroll
    for (int q = 0; q < ROWS_PER_BLOCK; q++)
        xs[q] = __ldg(x + b0 + q);
    const float4 s2q = *(const float4*)(s2 + jb + tid * 4);

#if __CUDA_ARCH__ >= 900
    cudaGridDependencySynchronize();              // wait for d_z
#endif

    // ---- load z (bits 0..4 & 10..12 already done): k regs = bits 5..6 ----
    float rr[4];
    #pragma unroll
    for (int k = 0; k < 4; k++)
        rr[k] = d_z[jb + r * 128 + k * 32 + lane];

    { // bit 5 (k bit 0)
        float a0 = rr[0], c0 = rr[1], a1 = rr[2], c1 = rr[3];
        rr[0] = a0 + c0; rr[1] = a0 - c0;
        rr[2] = a1 + c1; rr[3] = a1 - c1;
    }
    { // bit 6 (k bit 1)
        float a0 = rr[0], c0 = rr[2], a1 = rr[1], c1 = rr[3];
        rr[0] = a0 + c0; rr[2] = a0 - c0;
        rr[1] = a1 + c1; rr[3] = a1 - c1;
    }

    // stage partials pre[c*128 + t] (c = this warp's r)
    #pragma unroll
    for (int k = 0; k < 4; k++)
        sw[r * 128 + k * 32 + lane] = rr[k];
    __syncthreads();

    // ---- bits 7..9: signed combine, conflict-free LDS.128 ----
    const int toff = lane * 4;                    // (tid*4) & 127
    float4 w4 = make_float4(0.f, 0.f, 0.f, 0.f);
    #pragma unroll
    for (int c = 0; c < 8; c++) {
        const float sgn = (__popc(r & c) & 1) ? -1.0f : 1.0f;   // warp-uniform
        const float4 p = *(const float4*)&sw[c * 128 + toff];
        w4.x = fmaf(sgn, p.x, w4.x);
        w4.y = fmaf(sgn, p.y, w4.y);
        w4.z = fmaf(sgn, p.z, w4.z);
        w4.w = fmaf(sgn, p.w, w4.w);
    }
    // s2 last (elementwise on the completed transform)
    w4.x *= s2q.x; w4.y *= s2q.y; w4.z *= s2q.z; w4.w *= s2q.w;

    const int jbase = jb + tid * 4;
    #pragma unroll
    for (int q = 0; q < ROWS_PER_BLOCK; q++) {
        float xv = xs[q];
        float4 o = make_float4(xv * w4.x, xv * w4.y, xv * w4.z, xv * w4.w);
        // 134 MB output, never re-read -> streaming (evict-first) store
        __stcs((float4*)(out + (size_t)(b0 + q) * D + jbase), o);
    }
}

extern "C" void kernel_launch(void* const* d_in, const int* in_sizes, int n_in,
                              void* d_out, int out_size) {
    const float* x     = (const float*)d_in[0];  // (4096, 1)
    const float* s1    = (const float*)d_in[1];  // (8192,)
    const float* s2    = (const float*)d_in[2];  // (8192,)
    const float* g_mu  = (const float*)d_in[3];  // (8192,)
    const float* g_rho = (const float*)d_in[4];  // (8192,)
    const float* eps   = (const float*)d_in[5];  // (8192,)
    float* out = (float*)d_out;                  // (4096, 8192) f32

    producer_kernel<<<16, 64>>>(s1, g_mu, g_rho, eps);

    cudaLaunchConfig_t cfg = {};
    cfg.gridDim  = dim3(D / 1024, BATCH / ROWS_PER_BLOCK, 1);  // (8, 256)
    cfg.blockDim = dim3(256, 1, 1);
    cfg.stream   = 0;
    cudaLaunchAttribute attr;
    attr.id = cudaLaunchAttributeProgrammaticStreamSerialization;
    attr.val.programmaticStreamSerializationAllowed = 1;
    cfg.attrs    = &attr;
    cfg.numAttrs = 1;
    cudaLaunchKernelEx(&cfg, outer_kernel, x, s2, out);
}